// round 3
// baseline (speedup 1.0000x reference)
#include <cuda_runtime.h>
#include <cuda_bf16.h>

// Problem constants
#define B_   16
#define T_   8
#define E_   2048
#define H_   16
#define HD_  128
#define S_   4096
#define ST_  4104            // S_ + T_
#define BT_  128             // B_*T_
#define N3E  6144            // 3*E_
#define NSPLIT 8
#define KEYS_PER_SPLIT 512   // S_/NSPLIT
#define SCALE_ 0.08838834764831845f  // hd^-0.5

// Output layout (floats): [out (B,T,E)][k (B,H,ST,HD)][v (B,H,ST,HD)]
#define OFF_K   262144
#define OFF_V   134742016
#define OFF_K4  65536        // OFF_K/4
#define OFF_V4  33685504     // OFF_V/4

// Scratch (static device globals; no allocation allowed)
__device__ float d_q[BT_ * E_];                       // (b,h,t,d), pre-scaled
__device__ float d_part_o[B_*H_*NSPLIT*T_*HD_];       // (bh,split,t,d)
__device__ float d_part_m[B_*H_*NSPLIT*T_];
__device__ float d_part_l[B_*H_*NSPLIT*T_];
__device__ float d_attn[BT_ * E_];                    // (b,t, h*HD+d)

typedef unsigned long long ULL;

__device__ __forceinline__ ULL pack2(float x, float y) {
    ULL r; asm("mov.b64 %0, {%1,%2};" : "=l"(r) : "f"(x), "f"(y)); return r;
}
__device__ __forceinline__ void ffma2(ULL& d, ULL a, ULL b) {
    asm("fma.rn.f32x2 %0, %1, %2, %0;" : "+l"(d) : "l"(a), "l"(b));
}
__device__ __forceinline__ void unpack2(ULL v, float& x, float& y) {
    asm("mov.b64 {%0,%1}, %2;" : "=f"(x), "=f"(y) : "l"(v));
}

// ---------------------------------------------------------------------------
// K1: QKV GEMM.  C(128 x 6144) = x(128 x 2048) @ w_qkv + b_qkv
// BM=128, BN=32, BK=16, 256 threads, micro-tile 8x2 via FFMA2 pairs.
// Epilogue scatters: q -> d_q (scaled), k_new/v_new -> output rows S..S+T-1.
// ---------------------------------------------------------------------------
__device__ __forceinline__ void qkv_scatter(int m, int n, float v, float* __restrict__ out) {
    int which = n >> 11;        // n / 2048
    int e = n & 2047;
    int h = e >> 7;
    int d = e & 127;
    int b = m >> 3;
    int t = m & 7;
    if (which == 0) {
        d_q[((b*H_ + h)*T_ + t)*HD_ + d] = v * SCALE_;
    } else if (which == 1) {
        out[OFF_K + ((size_t)((b*H_ + h)*ST_ + S_ + t))*HD_ + d] = v;
    } else {
        out[OFF_V + ((size_t)((b*H_ + h)*ST_ + S_ + t))*HD_ + d] = v;
    }
}

__global__ __launch_bounds__(256) void qkv_gemm(
    const float* __restrict__ x, const float* __restrict__ w,
    const float* __restrict__ bias, float* __restrict__ out)
{
    __shared__ __align__(16) float As[16*132];   // As[k][m], stride 132
    __shared__ __align__(16) float Bs[16*36];    // Bs[k][n], stride 36

    const int tid = threadIdx.x;
    const int bn  = blockIdx.x;          // 0..191, n0 = bn*32
    const int tx  = tid & 15;            // n micro
    const int ty  = tid >> 4;            // m micro

    const float4* x4 = (const float4*)x;     // row stride 512 f4
    const float4* w4 = (const float4*)w;     // row stride 1536 f4

    ULL acc[4][2];
    #pragma unroll
    for (int i = 0; i < 4; i++) { acc[i][0] = 0ULL; acc[i][1] = 0ULL; }

    const int lm = tid >> 2;   // 0..63
    const int kq = tid & 3;

    // prefetch tile 0
    float4 ra0 = x4[(size_t)lm*512 + kq];
    float4 ra1 = x4[(size_t)(64 + lm)*512 + kq];
    float4 rb;
    if (tid < 128) rb = w4[(size_t)(tid >> 3)*1536 + bn*8 + (tid & 7)];

    for (int kt = 0; kt < 128; kt++) {
        // store prefetched tile to shared
        As[(kq*4+0)*132 + lm] = ra0.x;
        As[(kq*4+1)*132 + lm] = ra0.y;
        As[(kq*4+2)*132 + lm] = ra0.z;
        As[(kq*4+3)*132 + lm] = ra0.w;
        As[(kq*4+0)*132 + 64 + lm] = ra1.x;
        As[(kq*4+1)*132 + 64 + lm] = ra1.y;
        As[(kq*4+2)*132 + 64 + lm] = ra1.z;
        As[(kq*4+3)*132 + 64 + lm] = ra1.w;
        if (tid < 128) ((float4*)Bs)[(tid >> 3)*9 + (tid & 7)] = rb;
        __syncthreads();

        // prefetch next tile
        if (kt + 1 < 128) {
            int kb = (kt + 1)*4;
            ra0 = x4[(size_t)lm*512 + kb + kq];
            ra1 = x4[(size_t)(64 + lm)*512 + kb + kq];
            if (tid < 128) rb = w4[(size_t)((kt+1)*16 + (tid >> 3))*1536 + bn*8 + (tid & 7)];
        }

        #pragma unroll
        for (int k = 0; k < 16; k++) {
            const float* Ap = &As[k*132 + ty*8];
            ULL a0 = *(const ULL*)(Ap + 0);
            ULL a1 = *(const ULL*)(Ap + 2);
            ULL a2 = *(const ULL*)(Ap + 4);
            ULL a3 = *(const ULL*)(Ap + 6);
            float2 bb = *(const float2*)&Bs[k*36 + tx*2];
            ULL b0 = pack2(bb.x, bb.x);
            ULL b1 = pack2(bb.y, bb.y);
            ffma2(acc[0][0], a0, b0); ffma2(acc[0][1], a0, b1);
            ffma2(acc[1][0], a1, b0); ffma2(acc[1][1], a1, b1);
            ffma2(acc[2][0], a2, b0); ffma2(acc[2][1], a2, b1);
            ffma2(acc[3][0], a3, b0); ffma2(acc[3][1], a3, b1);
        }
        __syncthreads();
    }

    #pragma unroll
    for (int i = 0; i < 4; i++) {
        #pragma unroll
        for (int j = 0; j < 2; j++) {
            float lo, hi;
            unpack2(acc[i][j], lo, hi);
            int n = bn*32 + tx*2 + j;
            float bv = bias[n];
            int m = ty*8 + 2*i;
            qkv_scatter(m,     n, lo + bv, out);
            qkv_scatter(m + 1, n, hi + bv, out);
        }
    }
}

// ---------------------------------------------------------------------------
// K2: fused cache copy + split-KV partial attention.
// grid 2048 = (bh=256) x (split=8), 256 threads. Each block streams 512
// cached K rows + 512 V rows: copies them to the output k/v tensors AND
// runs online-softmax attention for the 8 queries of (b,h).
// ---------------------------------------------------------------------------
__global__ __launch_bounds__(256) void attn_partial(
    const float* __restrict__ ck, const float* __restrict__ cv,
    float* __restrict__ out)
{
    const int blk   = blockIdx.x;
    const int bh    = blk >> 3;
    const int split = blk & 7;
    const int tid   = threadIdx.x;

    __shared__ __align__(16) float4 q4s[T_ * 32];        // [t][d4]
    __shared__ __align__(16) float4 k4s[32 * 33];        // [j][c], stride 33 f4
    __shared__ __align__(16) float4 v4s[32 * 33];
    __shared__ __align__(16) float  s_sh[T_ * 33];       // scores/probs, stride 33
    __shared__ float  m_sh[T_], l_sh[T_], a_sh[T_];

    const float4* ck4 = (const float4*)ck;
    const float4* cv4 = (const float4*)cv;
    float4* out4 = (float4*)out;
    const float4* q4 = (const float4*)d_q;

    // load q (pre-scaled), init state
    q4s[tid] = q4[(size_t)bh*256 + tid];
    if (tid < T_) { m_sh[tid] = -1e30f; l_sh[tid] = 0.0f; }

    const int w    = tid >> 5;
    const int lane = tid & 31;
    const int ot   = lane >> 2;             // PV: query owned
    const int oc4  = w*4 + (lane & 3);      // PV: f4-chunk of head dim
    const int sj   = tid >> 3;              // score: key
    const int st   = tid & 7;               // score: query
    const int s_base = split * KEYS_PER_SPLIT;

    float4 o = make_float4(0.f, 0.f, 0.f, 0.f);
    __syncthreads();

    for (int tile = 0; tile < 16; tile++) {
        const int s0 = s_base + tile*32;

        // ---- load K,V tile (global -> regs -> out copy + shared) ----
        #pragma unroll
        for (int i = 0; i < 4; i++) {
            int id = tid + 256*i;
            int j = id >> 5, c = id & 31;
            size_t src = ((size_t)bh*S_ + s0 + j)*32 + c;
            size_t dst = ((size_t)bh*ST_ + s0 + j)*32 + c;
            float4 kk = ck4[src];
            float4 vv = cv4[src];
            out4[OFF_K4 + dst] = kk;
            out4[OFF_V4 + dst] = vv;
            k4s[j*33 + c] = kk;
            v4s[j*33 + c] = vv;
        }
        __syncthreads();

        // ---- scores: thread (j=sj, t=st) ----
        {
            float4 acc = make_float4(0.f, 0.f, 0.f, 0.f);
            #pragma unroll
            for (int c = 0; c < 32; c++) {
                float4 kk = k4s[sj*33 + c];
                float4 qq = q4s[st*32 + c];
                acc.x = fmaf(kk.x, qq.x, acc.x);
                acc.y = fmaf(kk.y, qq.y, acc.y);
                acc.z = fmaf(kk.z, qq.z, acc.z);
                acc.w = fmaf(kk.w, qq.w, acc.w);
            }
            s_sh[st*33 + sj] = (acc.x + acc.y) + (acc.z + acc.w);
        }
        __syncthreads();

        // ---- online softmax update: warp w handles query t=w ----
        {
            const int t = w, j = lane;
            float sc = s_sh[t*33 + j];
            float mt = sc;
            #pragma unroll
            for (int off = 16; off; off >>= 1)
                mt = fmaxf(mt, __shfl_xor_sync(0xffffffffu, mt, off));
            float m_old = m_sh[t];
            float m_new = fmaxf(m_old, mt);
            float p = __expf(sc - m_new);
            s_sh[t*33 + j] = p;
            float ps = p;
            #pragma unroll
            for (int off = 16; off; off >>= 1)
                ps += __shfl_xor_sync(0xffffffffu, ps, off);
            if (lane == 0) {
                float al = __expf(m_old - m_new);
                l_sh[t] = l_sh[t]*al + ps;
                m_sh[t] = m_new;
                a_sh[t] = al;
            }
        }
        __syncthreads();

        // ---- PV accumulate: thread (ot, oc4) owns (query, f4-chunk) ----
        {
            float al = a_sh[ot];
            o.x *= al; o.y *= al; o.z *= al; o.w *= al;
            #pragma unroll
            for (int j = 0; j < 32; j++) {
                float p = s_sh[ot*33 + j];
                float4 vv = v4s[j*33 + oc4];
                o.x = fmaf(p, vv.x, o.x);
                o.y = fmaf(p, vv.y, o.y);
                o.z = fmaf(p, vv.z, o.z);
                o.w = fmaf(p, vv.w, o.w);
            }
        }
        __syncthreads();
    }

    // write partials
    float4* po4 = (float4*)d_part_o;
    po4[((size_t)blk*T_ + ot)*32 + oc4] = o;
    if (tid < T_) {
        d_part_m[blk*T_ + tid] = m_sh[tid];
        d_part_l[blk*T_ + tid] = l_sh[tid];
    }
}

// ---------------------------------------------------------------------------
// K3: combine partials + causal-masked new keys. grid 256 (bh), 256 thr.
// warp t handles query t; lane owns f4-chunk `lane` of the 128 head dims.
// ---------------------------------------------------------------------------
__global__ __launch_bounds__(256) void attn_combine(const float* __restrict__ out_ro)
{
    const int bh   = blockIdx.x;
    const int t    = threadIdx.x >> 5;
    const int lane = threadIdx.x & 31;

    const float4* q4 = (const float4*)d_q;
    const float4* o4 = (const float4*)out_ro;
    const float4* po4 = (const float4*)d_part_o;

    float4 qv = q4[(size_t)(bh*T_ + t)*32 + lane];

    // new-key scores (causal: key j allowed iff j <= t)
    float sj[T_];
    float m_new = -1e30f;
    #pragma unroll
    for (int j = 0; j < T_; j++) {
        float sc = -1e30f;
        if (j <= t) {
            float4 kv = o4[OFF_K4 + ((size_t)bh*ST_ + S_ + j)*32 + lane];
            float p = qv.x*kv.x + qv.y*kv.y + qv.z*kv.z + qv.w*kv.w;
            #pragma unroll
            for (int off = 16; off; off >>= 1)
                p += __shfl_xor_sync(0xffffffffu, p, off);
            sc = p;
        }
        sj[j] = sc;
        m_new = fmaxf(m_new, sc);
    }

    float pm[NSPLIT], pl[NSPLIT];
    #pragma unroll
    for (int s = 0; s < NSPLIT; s++) {
        pm[s] = d_part_m[(bh*NSPLIT + s)*T_ + t];
        pl[s] = d_part_l[(bh*NSPLIT + s)*T_ + t];
        m_new = fmaxf(m_new, pm[s]);
    }

    float denom = 0.0f;
    float4 acc = make_float4(0.f, 0.f, 0.f, 0.f);
    #pragma unroll
    for (int s = 0; s < NSPLIT; s++) {
        float ws = __expf(pm[s] - m_new);
        denom += ws * pl[s];
        float4 po = po4[((size_t)(bh*NSPLIT + s)*T_ + t)*32 + lane];
        acc.x = fmaf(ws, po.x, acc.x);
        acc.y = fmaf(ws, po.y, acc.y);
        acc.z = fmaf(ws, po.z, acc.z);
        acc.w = fmaf(ws, po.w, acc.w);
    }
    #pragma unroll
    for (int j = 0; j < T_; j++) {
        if (j <= t) {
            float p = __expf(sj[j] - m_new);
            denom += p;
            float4 vv = o4[OFF_V4 + ((size_t)bh*ST_ + S_ + j)*32 + lane];
            acc.x = fmaf(p, vv.x, acc.x);
            acc.y = fmaf(p, vv.y, acc.y);
            acc.z = fmaf(p, vv.z, acc.z);
            acc.w = fmaf(p, vv.w, acc.w);
        }
    }

    float inv = 1.0f / denom;
    acc.x *= inv; acc.y *= inv; acc.z *= inv; acc.w *= inv;

    float4* a4 = (float4*)d_attn;
    int b = bh >> 4, h = bh & 15;
    a4[((size_t)(b*T_ + t))*512 + h*32 + lane] = acc;
}

// ---------------------------------------------------------------------------
// K4: out projection. out(128 x 2048) = attn(128 x 2048) @ w_out + b_out
// BM=64, BN=32, BK=16, 256 threads, micro 4x2 FFMA2. grid (64, 2).
// ---------------------------------------------------------------------------
__global__ __launch_bounds__(256) void out_gemm(
    const float* __restrict__ wo, const float* __restrict__ bo,
    float* __restrict__ out)
{
    __shared__ __align__(16) float As[16*68];
    __shared__ __align__(16) float Bs[16*36];

    const int tid = threadIdx.x;
    const int tx = tid & 15, ty = tid >> 4;
    const int bx = blockIdx.x;          // n0 = bx*32
    const int m0 = blockIdx.y * 64;

    const float4* a4 = (const float4*)d_attn;   // row stride 512 f4
    const float4* w4 = (const float4*)wo;       // row stride 512 f4

    ULL acc[2][2];
    acc[0][0] = acc[0][1] = acc[1][0] = acc[1][1] = 0ULL;

    const int lm = tid >> 2;  // 0..63
    const int kq = tid & 3;

    float4 ra = a4[(size_t)(m0 + lm)*512 + kq];
    float4 rb;
    if (tid < 128) rb = w4[(size_t)(tid >> 3)*512 + bx*8 + (tid & 7)];

    for (int kt = 0; kt < 128; kt++) {
        As[(kq*4+0)*68 + lm] = ra.x;
        As[(kq*4+1)*68 + lm] = ra.y;
        As[(kq*4+2)*68 + lm] = ra.z;
        As[(kq*4+3)*68 + lm] = ra.w;
        if (tid < 128) ((float4*)Bs)[(tid >> 3)*9 + (tid & 7)] = rb;
        __syncthreads();

        if (kt + 1 < 128) {
            ra = a4[(size_t)(m0 + lm)*512 + (kt+1)*4 + kq];
            if (tid < 128) rb = w4[(size_t)((kt+1)*16 + (tid >> 3))*512 + bx*8 + (tid & 7)];
        }

        #pragma unroll
        for (int k = 0; k < 16; k++) {
            const float* Ap = &As[k*68 + ty*4];
            ULL a0 = *(const ULL*)(Ap + 0);
            ULL a1 = *(const ULL*)(Ap + 2);
            float2 bb = *(const float2*)&Bs[k*36 + tx*2];
            ULL b0 = pack2(bb.x, bb.x);
            ULL b1 = pack2(bb.y, bb.y);
            ffma2(acc[0][0], a0, b0); ffma2(acc[0][1], a0, b1);
            ffma2(acc[1][0], a1, b0); ffma2(acc[1][1], a1, b1);
        }
        __syncthreads();
    }

    #pragma unroll
    for (int i = 0; i < 2; i++) {
        #pragma unroll
        for (int j = 0; j < 2; j++) {
            float lo, hi;
            unpack2(acc[i][j], lo, hi);
            int n = bx*32 + tx*2 + j;
            float bv = bo[n];
            int m = m0 + ty*4 + 2*i;
            out[(size_t)m*E_ + n]       = lo + bv;
            out[(size_t)(m+1)*E_ + n]   = hi + bv;
        }
    }
}

// ---------------------------------------------------------------------------
extern "C" void kernel_launch(void* const* d_in, const int* in_sizes, int n_in,
                              void* d_out, int out_size)
{
    const float* x      = (const float*)d_in[0];
    const float* ck     = (const float*)d_in[1];
    const float* cv     = (const float*)d_in[2];
    const float* w_qkv  = (const float*)d_in[3];
    const float* b_qkv  = (const float*)d_in[4];
    const float* w_out  = (const float*)d_in[5];
    const float* b_out  = (const float*)d_in[6];
    float* out = (float*)d_out;

    qkv_gemm<<<192, 256>>>(x, w_qkv, b_qkv, out);
    attn_partial<<<B_*H_*NSPLIT, 256>>>(ck, cv, out);
    attn_combine<<<B_*H_, 256>>>(out);
    out_gemm<<<dim3(64, 2), 256>>>(w_out, b_out, out);
}

// round 4
// speedup vs baseline: 2.6862x; 2.6862x over previous
#include <cuda_runtime.h>
#include <cuda_bf16.h>

// Problem constants
#define B_   16
#define T_   8
#define E_   2048
#define H_   16
#define HD_  128
#define S_   4096
#define ST_  4104            // S_ + T_
#define BT_  128             // B_*T_
#define NSPLIT 16
#define KPS  256             // keys per split = S_/NSPLIT
#define SPLITK 8
#define SCALE_ 0.08838834764831845f  // hd^-0.5

// Output layout (floats): [out (B,T,E)][k (B,H,ST,HD)][v (B,H,ST,HD)]
#define OFF_K   262144
#define OFF_V   134742016
#define OFF_K4  65536        // OFF_K/4
#define OFF_V4  33685504     // OFF_V/4

// Scratch (static device globals; no allocation allowed)
__device__ float d_q[BT_ * E_];                       // (b,h,t,d), pre-scaled
__device__ float d_part_o[B_*H_*NSPLIT*T_*HD_];       // (blk,t,d)
__device__ float d_part_m[B_*H_*NSPLIT*T_];
__device__ float d_part_l[B_*H_*NSPLIT*T_];
__device__ float d_attn[BT_ * E_];                    // (b,t, h*HD+d)
__device__ float d_p1[SPLITK*128*6144];               // qkv gemm partials
__device__ float d_p2[SPLITK*128*2048];               // out gemm partials

typedef unsigned long long ULL;

__device__ __forceinline__ ULL pack2(float x, float y) {
    ULL r; asm("mov.b64 %0, {%1,%2};" : "=l"(r) : "f"(x), "f"(y)); return r;
}
__device__ __forceinline__ void ffma2(ULL& d, ULL a, ULL b) {
    asm("fma.rn.f32x2 %0, %1, %2, %0;" : "+l"(d) : "l"(a), "l"(b));
}

// ---------------------------------------------------------------------------
// Generic GEMM: part[split][128][N] = A[128, kchunk slice] @ W[kchunk, N]
// BM=128, BN=128, BK=16, 256 threads, 8x8 micro-tile via FFMA2.
// grid (N/128, SPLITK). A_ext==nullptr -> use d_attn. use_p2 selects buffer.
// ---------------------------------------------------------------------------
__global__ __launch_bounds__(256) void gemm128(
    const float* __restrict__ A_ext, const float* __restrict__ W,
    int N, int K, int use_p2)
{
    __shared__ __align__(16) float As[16*132];   // As[k][m], stride 132
    __shared__ __align__(16) float Bs[16*136];   // Bs[k][n], stride 136

    const float* __restrict__ A = A_ext ? A_ext : (const float*)d_attn;
    float* part = use_p2 ? d_p2 : d_p1;

    const int tid = threadIdx.x;
    const int tx = tid & 15, ty = tid >> 4;
    const int n0 = blockIdx.x * 128;
    const int kchunk = K / SPLITK;
    const int k0 = blockIdx.y * kchunk;
    const int kiters = kchunk / 16;

    const int Kf4 = K >> 2, Nf4 = N >> 2;
    const float4* A4 = (const float4*)A;
    const float4* W4 = (const float4*)W;

    const int r = tid >> 2, q = tid & 3;

    ULL acc[8][4];
    #pragma unroll
    for (int m = 0; m < 8; m++)
        #pragma unroll
        for (int np = 0; np < 4; np++) acc[m][np] = 0ULL;

    // prefetch tile 0
    float4 ra0 = A4[(size_t)r*Kf4 + (k0 >> 2) + q];
    float4 ra1 = A4[(size_t)(r + 64)*Kf4 + (k0 >> 2) + q];
    float4 rb0 = W4[(size_t)(k0 + ty)*Nf4 + (n0 >> 2) + tx*2];
    float4 rb1 = W4[(size_t)(k0 + ty)*Nf4 + (n0 >> 2) + tx*2 + 1];

    for (int kt = 0; kt < kiters; kt++) {
        As[(q*4+0)*132 + r] = ra0.x;
        As[(q*4+1)*132 + r] = ra0.y;
        As[(q*4+2)*132 + r] = ra0.z;
        As[(q*4+3)*132 + r] = ra0.w;
        As[(q*4+0)*132 + 64 + r] = ra1.x;
        As[(q*4+1)*132 + 64 + r] = ra1.y;
        As[(q*4+2)*132 + 64 + r] = ra1.z;
        As[(q*4+3)*132 + 64 + r] = ra1.w;
        ((float4*)Bs)[ty*34 + tx*2]     = rb0;
        ((float4*)Bs)[ty*34 + tx*2 + 1] = rb1;
        __syncthreads();

        if (kt + 1 < kiters) {
            int kb = k0 + (kt + 1)*16;
            ra0 = A4[(size_t)r*Kf4 + (kb >> 2) + q];
            ra1 = A4[(size_t)(r + 64)*Kf4 + (kb >> 2) + q];
            rb0 = W4[(size_t)(kb + ty)*Nf4 + (n0 >> 2) + tx*2];
            rb1 = W4[(size_t)(kb + ty)*Nf4 + (n0 >> 2) + tx*2 + 1];
        }

        #pragma unroll
        for (int k = 0; k < 16; k++) {
            float4 alo = *(const float4*)&As[k*132 + ty*8];
            float4 ahi = *(const float4*)&As[k*132 + ty*8 + 4];
            float4 blo = *(const float4*)&Bs[k*136 + tx*8];
            float4 bhi = *(const float4*)&Bs[k*136 + tx*8 + 4];
            ULL bp0 = pack2(blo.x, blo.y), bp1 = pack2(blo.z, blo.w);
            ULL bp2 = pack2(bhi.x, bhi.y), bp3 = pack2(bhi.z, bhi.w);
            float am[8] = {alo.x, alo.y, alo.z, alo.w, ahi.x, ahi.y, ahi.z, ahi.w};
            #pragma unroll
            for (int m = 0; m < 8; m++) {
                ULL as = pack2(am[m], am[m]);
                ffma2(acc[m][0], as, bp0);
                ffma2(acc[m][1], as, bp1);
                ffma2(acc[m][2], as, bp2);
                ffma2(acc[m][3], as, bp3);
            }
        }
        __syncthreads();
    }

    float* pbase = part + (size_t)blockIdx.y*128*N;
    #pragma unroll
    for (int m = 0; m < 8; m++) {
        int row = ty*8 + m;
        float2* p2 = (float2*)(pbase + (size_t)row*N + n0 + tx*8);
        #pragma unroll
        for (int np = 0; np < 4; np++)
            p2[np] = *(float2*)&acc[m][np];
    }
}

// ---------------------------------------------------------------------------
// Reduce QKV partials: sum 8 splits + bias, scatter q (scaled) / k_new / v_new
// grid 768 x 256: one float4 (= 4 consecutive n, same m) per thread.
// ---------------------------------------------------------------------------
__global__ __launch_bounds__(256) void reduce_qkv(
    const float* __restrict__ bias, float* __restrict__ out)
{
    const int idx = blockIdx.x*256 + threadIdx.x;    // 0..196607
    const int m = idx / 1536, c4 = idx - m*1536;
    const float4* p4 = (const float4*)d_p1;
    float4 s = p4[idx];
    #pragma unroll
    for (int sp = 1; sp < SPLITK; sp++) {
        float4 tt = p4[sp*196608 + idx];
        s.x += tt.x; s.y += tt.y; s.z += tt.z; s.w += tt.w;
    }
    float4 bv = ((const float4*)bias)[c4];
    s.x += bv.x; s.y += bv.y; s.z += bv.z; s.w += bv.w;

    const int n = c4*4;
    const int which = n >> 11, e = n & 2047, h = e >> 7, d = e & 127;
    const int b = m >> 3, t = m & 7;
    if (which == 0) {
        s.x *= SCALE_; s.y *= SCALE_; s.z *= SCALE_; s.w *= SCALE_;
        ((float4*)d_q)[((b*H_ + h)*T_ + t)*32 + (d >> 2)] = s;
    } else if (which == 1) {
        ((float4*)out)[OFF_K4 + ((size_t)((b*H_ + h)*ST_ + S_ + t))*32 + (d >> 2)] = s;
    } else {
        ((float4*)out)[OFF_V4 + ((size_t)((b*H_ + h)*ST_ + S_ + t))*32 + (d >> 2)] = s;
    }
}

// ---------------------------------------------------------------------------
// Reduce out-proj partials: sum 8 splits + bias -> out[0 .. 128*2048)
// grid 256 x 256: one float4 per thread.
// ---------------------------------------------------------------------------
__global__ __launch_bounds__(256) void reduce_out(
    const float* __restrict__ bias, float* __restrict__ out)
{
    const int idx = blockIdx.x*256 + threadIdx.x;    // 0..65535
    const float4* p4 = (const float4*)d_p2;
    float4 s = p4[idx];
    #pragma unroll
    for (int sp = 1; sp < SPLITK; sp++) {
        float4 tt = p4[sp*65536 + idx];
        s.x += tt.x; s.y += tt.y; s.z += tt.z; s.w += tt.w;
    }
    const int c4 = idx & 511;
    float4 bv = ((const float4*)bias)[c4];
    s.x += bv.x; s.y += bv.y; s.z += bv.z; s.w += bv.w;
    ((float4*)out)[idx] = s;
}

// ---------------------------------------------------------------------------
// K2: fused cache copy + split-KV partial attention, pipelined.
// grid 4096 = (bh=256) x (split=16), 256 threads. Block streams 256 K rows +
// 256 V rows: copies to output k/v AND runs online softmax for 8 queries.
// Per 32-key tile: [regs->smem + copy-out STG] bar [prefetch next tile LDG;
// warp-per-query score+softmax in regs] bar [PV update] bar.
// ---------------------------------------------------------------------------
__global__ __launch_bounds__(256) void attn_partial(
    const float* __restrict__ ck, const float* __restrict__ cv,
    float* __restrict__ out)
{
    const int blk   = blockIdx.x;
    const int bh    = blk >> 4;
    const int split = blk & 15;
    const int tid   = threadIdx.x;

    __shared__ __align__(16) float4 q4s[T_ * 32];    // [t][d4]
    __shared__ __align__(16) float4 k4s[32 * 33];    // [j][c], stride 33
    __shared__ __align__(16) float4 v4s[32 * 33];
    __shared__ float  s_sh[T_ * 33];                 // probs, stride 33
    __shared__ float  a_sh[T_];

    const float4* ck4 = (const float4*)ck;
    const float4* cv4 = (const float4*)cv;
    float4* out4 = (float4*)out;
    const float4* q4 = (const float4*)d_q;

    const int w    = tid >> 5;              // warp = query for score phase
    const int lane = tid & 31;
    const int ot   = lane >> 2;             // PV: query owned
    const int oc4  = w*4 + (lane & 3);      // PV: f4-chunk of head dim
    const int s_base = split * KPS;

    q4s[tid] = q4[(size_t)bh*256 + tid];

    float m_cur = -1e30f, l_cur = 0.0f;
    float4 o = make_float4(0.f, 0.f, 0.f, 0.f);

    // prefetch tile 0 into regs: thread handles rows {w, w+8, w+16, w+24}, col lane
    float4 kk[4], vv[4];
    #pragma unroll
    for (int i = 0; i < 4; i++) {
        size_t src = ((size_t)bh*S_ + s_base + w + 8*i)*32 + lane;
        kk[i] = ck4[src]; vv[i] = cv4[src];
    }

    for (int tile = 0; tile < 8; tile++) {
        const int s0 = s_base + tile*32;

        // commit prefetched tile: copy-out + stage to shared
        #pragma unroll
        for (int i = 0; i < 4; i++) {
            int j = w + 8*i;
            size_t dst = ((size_t)bh*ST_ + s0 + j)*32 + lane;
            out4[OFF_K4 + dst] = kk[i];
            out4[OFF_V4 + dst] = vv[i];
            k4s[j*33 + lane] = kk[i];
            v4s[j*33 + lane] = vv[i];
        }
        __syncthreads();

        // prefetch next tile (overlaps with compute below)
        if (tile < 7) {
            #pragma unroll
            for (int i = 0; i < 4; i++) {
                size_t src = ((size_t)bh*S_ + s0 + 32 + w + 8*i)*32 + lane;
                kk[i] = ck4[src]; vv[i] = cv4[src];
            }
        }

        // scores + online softmax: warp w = query w, lane = key j
        {
            float4 acc = make_float4(0.f, 0.f, 0.f, 0.f);
            #pragma unroll
            for (int c = 0; c < 32; c++) {
                float4 kv = k4s[lane*33 + c];
                float4 qq = q4s[w*32 + c];
                acc.x = fmaf(kv.x, qq.x, acc.x);
                acc.y = fmaf(kv.y, qq.y, acc.y);
                acc.z = fmaf(kv.z, qq.z, acc.z);
                acc.w = fmaf(kv.w, qq.w, acc.w);
            }
            float sc = (acc.x + acc.y) + (acc.z + acc.w);
            float mt = sc;
            #pragma unroll
            for (int off = 16; off; off >>= 1)
                mt = fmaxf(mt, __shfl_xor_sync(0xffffffffu, mt, off));
            float m_new = fmaxf(m_cur, mt);
            float p = __expf(sc - m_new);
            float ps = p;
            #pragma unroll
            for (int off = 16; off; off >>= 1)
                ps += __shfl_xor_sync(0xffffffffu, ps, off);
            float al = __expf(m_cur - m_new);
            l_cur = l_cur*al + ps;
            m_cur = m_new;
            s_sh[w*33 + lane] = p;
            if (lane == 0) a_sh[w] = al;
        }
        __syncthreads();

        // PV accumulate: thread (ot, oc4)
        {
            float al = a_sh[ot];
            o.x *= al; o.y *= al; o.z *= al; o.w *= al;
            #pragma unroll
            for (int j = 0; j < 32; j++) {
                float p = s_sh[ot*33 + j];
                float4 vval = v4s[j*33 + oc4];
                o.x = fmaf(p, vval.x, o.x);
                o.y = fmaf(p, vval.y, o.y);
                o.z = fmaf(p, vval.z, o.z);
                o.w = fmaf(p, vval.w, o.w);
            }
        }
        __syncthreads();
    }

    ((float4*)d_part_o)[((size_t)blk*T_ + ot)*32 + oc4] = o;
    if (lane == 0) {
        d_part_m[blk*T_ + w] = m_cur;
        d_part_l[blk*T_ + w] = l_cur;
    }
}

// ---------------------------------------------------------------------------
// K3: combine 16 split partials + causal-masked new keys. grid 256 (bh).
// warp t handles query t; lane owns f4-chunk `lane` of the 128 head dims.
// ---------------------------------------------------------------------------
__global__ __launch_bounds__(256) void attn_combine(const float* __restrict__ out_ro)
{
    const int bh   = blockIdx.x;
    const int t    = threadIdx.x >> 5;
    const int lane = threadIdx.x & 31;

    const float4* q4 = (const float4*)d_q;
    const float4* o4 = (const float4*)out_ro;
    const float4* po4 = (const float4*)d_part_o;

    float4 qv = q4[(size_t)(bh*T_ + t)*32 + lane];

    // new-key scores (causal: key j allowed iff j <= t)
    float sj[T_];
    float m_new = -1e30f;
    #pragma unroll
    for (int j = 0; j < T_; j++) {
        float sc = -1e30f;
        if (j <= t) {
            float4 kv = o4[OFF_K4 + ((size_t)bh*ST_ + S_ + j)*32 + lane];
            float p = qv.x*kv.x + qv.y*kv.y + qv.z*kv.z + qv.w*kv.w;
            #pragma unroll
            for (int off = 16; off; off >>= 1)
                p += __shfl_xor_sync(0xffffffffu, p, off);
            sc = p;
        }
        sj[j] = sc;
        m_new = fmaxf(m_new, sc);
    }

    float pm[NSPLIT], pl[NSPLIT];
    #pragma unroll
    for (int s = 0; s < NSPLIT; s++) {
        pm[s] = d_part_m[(bh*NSPLIT + s)*T_ + t];
        pl[s] = d_part_l[(bh*NSPLIT + s)*T_ + t];
        m_new = fmaxf(m_new, pm[s]);
    }

    float denom = 0.0f;
    float4 acc = make_float4(0.f, 0.f, 0.f, 0.f);
    #pragma unroll
    for (int s = 0; s < NSPLIT; s++) {
        float ws = __expf(pm[s] - m_new);
        denom += ws * pl[s];
        float4 po = po4[((size_t)(bh*NSPLIT + s)*T_ + t)*32 + lane];
        acc.x = fmaf(ws, po.x, acc.x);
        acc.y = fmaf(ws, po.y, acc.y);
        acc.z = fmaf(ws, po.z, acc.z);
        acc.w = fmaf(ws, po.w, acc.w);
    }
    #pragma unroll
    for (int j = 0; j < T_; j++) {
        if (j <= t) {
            float p = __expf(sj[j] - m_new);
            denom += p;
            float4 vv = o4[OFF_V4 + ((size_t)bh*ST_ + S_ + j)*32 + lane];
            acc.x = fmaf(p, vv.x, acc.x);
            acc.y = fmaf(p, vv.y, acc.y);
            acc.z = fmaf(p, vv.z, acc.z);
            acc.w = fmaf(p, vv.w, acc.w);
        }
    }

    float inv = 1.0f / denom;
    acc.x *= inv; acc.y *= inv; acc.z *= inv; acc.w *= inv;

    float4* a4 = (float4*)d_attn;
    int b = bh >> 4, h = bh & 15;
    a4[((size_t)(b*T_ + t))*512 + h*32 + lane] = acc;
}

// ---------------------------------------------------------------------------
extern "C" void kernel_launch(void* const* d_in, const int* in_sizes, int n_in,
                              void* d_out, int out_size)
{
    const float* x      = (const float*)d_in[0];
    const float* ck     = (const float*)d_in[1];
    const float* cv     = (const float*)d_in[2];
    const float* w_qkv  = (const float*)d_in[3];
    const float* b_qkv  = (const float*)d_in[4];
    const float* w_out  = (const float*)d_in[5];
    const float* b_out  = (const float*)d_in[6];
    float* out = (float*)d_out;

    gemm128<<<dim3(48, SPLITK), 256>>>(x, w_qkv, 6144, 2048, 0);
    reduce_qkv<<<768, 256>>>(b_qkv, out);
    attn_partial<<<B_*H_*NSPLIT, 256>>>(ck, cv, out);
    attn_combine<<<B_*H_, 256>>>(out);
    gemm128<<<dim3(16, SPLITK), 256>>>(nullptr, w_out, 2048, 2048, 1);
    reduce_out<<<256, 256>>>(b_out, out);
}